// round 16
// baseline (speedup 1.0000x reference)
#include <cuda_runtime.h>
#include <cuda_fp16.h>
#include <math.h>
#include <stdint.h>

#define E   1024
#define NH  16
#define HD  64
#define FFD 4096
#define NL  6
#define VO  32000
#define BB  32
#define TT  100
#define SS  99
#define NTOK (BB*SS)   // 3168

// ---------------- scratch (static device globals; no runtime alloc) ----------------
__device__ float g_x[NTOK*E];
__device__ float g_qkv[NTOK*3*E];
__device__ float g_y[NTOK*E];
__device__ float g_y2[NTOK*E];                 // split-K slice-1 partials
__device__ float g_cav[NL*BB*E];
__device__ float g_cao[NL*BB*E];
__device__ float g_zbias[4096];                // zero-initialized (device globals)
__device__ __half g_abf[(size_t)NTOK*E];       // x fp16 buffer (plain)
__device__ __half g_cbf[(size_t)NTOK*E];       // attn ctx fp16 buffer (plain)
__device__ __half g_hbf[(size_t)NTOK*FFD];     // ff1 output fp16 buffer (plain)

// ============================================================================
// PTX helpers (mma.sync / ldmatrix / cp.async — all plain sm_80+ PTX)
// ============================================================================
__device__ __forceinline__ uint32_t smem_u32(const void* p) {
    return (uint32_t)__cvta_generic_to_shared(p);
}
__device__ __forceinline__ void cpa16(uint32_t dst, const void* src, uint32_t sz) {
    asm volatile("cp.async.cg.shared.global [%0], [%1], 16, %2;"
                 :: "r"(dst), "l"(src), "r"(sz) : "memory");
}
__device__ __forceinline__ void cpa_commit() {
    asm volatile("cp.async.commit_group;" ::: "memory");
}
__device__ __forceinline__ void cpa_wait1() {
    asm volatile("cp.async.wait_group 1;" ::: "memory");
}

#define LDSM4(r0, r1, r2, r3, addr) \
    asm volatile("ldmatrix.sync.aligned.m8n8.x4.shared.b16 {%0,%1,%2,%3}, [%4];" \
                 : "=r"(r0), "=r"(r1), "=r"(r2), "=r"(r3) : "r"(addr))

#define MMA16816(c, a, b0, b1) \
    asm volatile("mma.sync.aligned.m16n8k16.row.col.f32.f16.f16.f32 " \
                 "{%0,%1,%2,%3}, {%4,%5,%6,%7}, {%8,%9}, {%0,%1,%2,%3};" \
                 : "+f"((c)[0]), "+f"((c)[1]), "+f"((c)[2]), "+f"((c)[3]) \
                 : "r"((a)[0]), "r"((a)[1]), "r"((a)[2]), "r"((a)[3]), \
                   "r"(b0), "r"(b1))

// ============================================================================
// Tensor-core GEMM (HMMA), W read as fp32 and converted to fp16 in-kernel.
// C[M,N] = A[M,*]fp16 @ (fp16)W[N,*]fp32^T + bias, fp32 accumulate.
// MMA/ldmatrix/swizzle/epilogue identical to R9..R15-validated kernel; the
// B path stages fp32 via cp.async and converts (same __floats2half2_rn as the
// old cvt kernel -> bit-identical results). 3 stages of 64KB:
//   [0,16K)  A fp16    [16K,32K) B fp16 (swizzled)    [32K,64K) B fp32 staging
// Conversion of stage it+1 overlaps stage it's MMA section.
// K3 = k-extent this CTA iterates; sK = row stride (elements) of BOTH A and W.
//   non-split: gridDim.z=1, K3 == K.   split-K=2: gridDim.z=2, K3 = K/2.
// MODE 0: fp32 + bias (split-K aware)   MODE 1: ReLU + bias -> fp16 Ch
// MODE 2: fp32 + bias, logits row-remap into out[:,1:,:]
// ============================================================================
#define GST3 65536
#define GTC_SMEM3 (3*GST3)     // 192KB

template<int MODE>
__global__ void __launch_bounds__(256, 1)
gemm_tcw(const __half* __restrict__ A, const float* __restrict__ Wf,
         const float* __restrict__ bias, float* __restrict__ C,
         float* __restrict__ C2, __half* __restrict__ Ch,
         int M, int N, int K3, int sK) {
    extern __shared__ __align__(1024) char dsm[];
    const uint32_t smem = smem_u32(dsm);
    const int tid = threadIdx.x;
    const int warp = tid >> 5, lane = tid & 31;
    const int wm = warp >> 2, wn = warp & 3;
    const int bm = blockIdx.x * 128, bn = blockIdx.y * 128;

    // split-K slice selection
    const int zs = blockIdx.z;
    const __half* Ab = A + (size_t)zs * K3;
    const float*  Wb = Wf + (size_t)zs * K3;
    float* Cout = (zs == 0) ? C : C2;
    const float* bv = (zs == 0) ? bias : g_zbias;

    // ---- A fp16 load slots: 4 x 16B per thread
    const __half* ag[4]; uint32_t adst[4], asz[4];
#pragma unroll
    for (int j = 0; j < 4; j++) {
        int id = tid + j * 256;
        int r = id >> 3, c = id & 7;
        int gr = bm + r;
        bool v = gr < M;
        if (!v) gr = M - 1;
        ag[j] = Ab + (size_t)gr * sK + c * 8;
        asz[j] = v ? 16u : 0u;
        adst[j] = (uint32_t)(r * 128 + ((c ^ (r & 7)) << 4));
    }
    // ---- B fp32 load slots: 8 x 16B per thread into linear staging
    const float* bg[8]; uint32_t bfdst[8];
#pragma unroll
    for (int j = 0; j < 8; j++) {
        int id = tid + j * 256;
        int r = id >> 4, c = id & 15;
        bg[j] = Wb + (size_t)(bn + r) * sK + c * 4;
        bfdst[j] = 32768u + (uint32_t)(r * 256 + c * 16);
    }
    // ---- conversion slots: each thread produces 4 x 16B fp16 chunks
    uint32_t csrc[4], cdst[4];
#pragma unroll
    for (int j = 0; j < 4; j++) {
        int id = tid + j * 256;
        int r = id >> 3, c = id & 7;
        csrc[j] = (uint32_t)(32768 + r * 256 + c * 32);
        cdst[j] = (uint32_t)(16384 + r * 128 + ((c ^ (r & 7)) << 4));
    }

    auto convertB = [&](int stage) {
        char* sb = dsm + stage * GST3;
#pragma unroll
        for (int j = 0; j < 4; j++) {
            float4 f0 = *(const float4*)(sb + csrc[j]);
            float4 f1 = *(const float4*)(sb + csrc[j] + 16);
            __half2 h0 = __floats2half2_rn(f0.x, f0.y);
            __half2 h1 = __floats2half2_rn(f0.z, f0.w);
            __half2 h2 = __floats2half2_rn(f1.x, f1.y);
            __half2 h3 = __floats2half2_rn(f1.z, f1.w);
            uint4 u;
            u.x = *(uint32_t*)&h0; u.y = *(uint32_t*)&h1;
            u.z = *(uint32_t*)&h2; u.w = *(uint32_t*)&h3;
            *(uint4*)(sb + cdst[j]) = u;
        }
    };

    const int nIter = K3 >> 6;

    // prologue: stages 0,1 in flight
#pragma unroll
    for (int s = 0; s < 2; s++) {
        uint32_t sb = smem + s * GST3;
        int k0 = s * 64;
#pragma unroll
        for (int j = 0; j < 4; j++) cpa16(sb + adst[j], ag[j] + k0, asz[j]);
#pragma unroll
        for (int j = 0; j < 8; j++) cpa16(sb + bfdst[j], bg[j] + k0, 16);
        cpa_commit();
    }
    cpa_wait1();          // stage 0 arrived
    __syncthreads();      // visible to all threads
    convertB(0);
    __syncthreads();      // stage 0 fp16 ready

    // ---- ldmatrix address components (identical to validated kernel)
    uint32_t aoff[4], aswz[4];
#pragma unroll
    for (int mi = 0; mi < 4; mi++) {
        int rowa = wm * 64 + mi * 16 + (lane & 15);
        aoff[mi] = rowa * 128;
        aswz[mi] = rowa & 7;
    }
    const uint32_t ahi = lane >> 4;
    uint32_t boff[2], bswz[2];
#pragma unroll
    for (int p = 0; p < 2; p++) {
        int rowb = wn * 32 + p * 16 + (lane & 7) + ((lane >> 4) << 3);
        boff[p] = 16384 + rowb * 128;
        bswz[p] = rowb & 7;
    }
    const uint32_t bhi = (lane >> 3) & 1;

    float acc[4][4][4];
#pragma unroll
    for (int i = 0; i < 4; i++)
#pragma unroll
        for (int j = 0; j < 4; j++)
#pragma unroll
            for (int k = 0; k < 4; k++) acc[i][j][k] = 0.f;

    int stage = 0;
    for (int it = 0; it < nIter; it++) {
        // issue loads for stage it+2 (rotates into (it+2)%3 = (it-1)%3 slot;
        // that slot's fp16 was consumed in iter it-1, fp32 in iter it-2,
        // both sealed by the syncthreads at the end of iter it-1).
        int ld = it + 2;
        if (ld < nIter) {
            int ls = ld % 3;
            uint32_t sb = smem + ls * GST3;
            int k0 = ld * 64;
#pragma unroll
            for (int j = 0; j < 4; j++) cpa16(sb + adst[j], ag[j] + k0, asz[j]);
#pragma unroll
            for (int j = 0; j < 8; j++) cpa16(sb + bfdst[j], bg[j] + k0, 16);
        }
        cpa_commit();

        // MMA section on current stage (fp16 B already converted)
        const uint32_t sb = smem + stage * GST3;
#pragma unroll
        for (int ki = 0; ki < 4; ki++) {
            uint32_t a[4][4], b[2][4];
#pragma unroll
            for (int mi = 0; mi < 4; mi++) {
                uint32_t addr = sb + aoff[mi] + ((((ki << 1) + ahi) ^ aswz[mi]) << 4);
                LDSM4(a[mi][0], a[mi][1], a[mi][2], a[mi][3], addr);
            }
#pragma unroll
            for (int p = 0; p < 2; p++) {
                uint32_t addr = sb + boff[p] + ((((ki << 1) + bhi) ^ bswz[p]) << 4);
                LDSM4(b[p][0], b[p][1], b[p][2], b[p][3], addr);
            }
#pragma unroll
            for (int mi = 0; mi < 4; mi++) {
#pragma unroll
                for (int p = 0; p < 2; p++) {
                    MMA16816(acc[mi][2 * p],     a[mi], b[p][0], b[p][1]);
                    MMA16816(acc[mi][2 * p + 1], a[mi], b[p][2], b[p][3]);
                }
            }
        }

        // convert NEXT stage's B while tensor pipe drains
        cpa_wait1();          // stage it+1 arrived
        __syncthreads();      // its fp32 visible; prior ldmatrix complete
        if (it + 1 < nIter) convertB((it + 1) % 3);
        __syncthreads();      // conversion visible before next MMA section

        stage = (stage + 1) % 3;
    }

    // ---- epilogue (identical to validated kernel)
    const int r0 = bm + wm * 64 + (lane >> 2);
    const int cq = (lane & 3) * 2;
#pragma unroll
    for (int mi = 0; mi < 4; mi++) {
#pragma unroll
        for (int half = 0; half < 2; half++) {
            int row = r0 + mi * 16 + half * 8;
            if (row >= M) continue;
            size_t rowoff;
            if (MODE == 2) {
                int bI = row / SS, sI = row - bI * SS;
                rowoff = (size_t)(bI * TT + sI + 1) * (size_t)N;
            } else {
                rowoff = (size_t)row * (size_t)N;
            }
#pragma unroll
            for (int nt = 0; nt < 4; nt++) {
                int col = bn + wn * 32 + (nt >> 1) * 16 + (nt & 1) * 8 + cq;
                float2 bvv = *(const float2*)(bv + col);
                float vx = acc[mi][nt][2 * half + 0] + bvv.x;
                float vy = acc[mi][nt][2 * half + 1] + bvv.y;
                if (MODE == 1) {
                    vx = fmaxf(vx, 0.f); vy = fmaxf(vy, 0.f);
                    *(__half2*)(Ch + rowoff + col) = __floats2half2_rn(vx, vy);
                } else {
                    *(float2*)(Cout + rowoff + col) = make_float2(vx, vy);
                }
            }
        }
    }
}

// ============================================================================
// fp32 -> fp16 conversion (plain), grid-stride. (activations only now)
// ============================================================================
__global__ void cvt_plain(const float* __restrict__ in, __half* __restrict__ out,
                          int n4) {
    int stride = gridDim.x * 256;
    for (int i = blockIdx.x * 256 + threadIdx.x; i < n4; i += stride) {
        float4 v = ((const float4*)in)[i];
        __half2* o = (__half2*)(out + (size_t)i * 4);
        o[0] = __floats2half2_rn(v.x, v.y);
        o[1] = __floats2half2_rn(v.z, v.w);
    }
}

// ============================================================================
// small SIMT GEMM (batched): cross-attention GEMVs (M=32) — validated verbatim
// ============================================================================
__global__ void gemm_nt_b(const float* __restrict__ A0, const float* __restrict__ W0,
                          const float* __restrict__ bias0, float* __restrict__ C0,
                          int M, int N, int K,
                          long aS, long wS, long bS, long cS) {
    const float* A = A0 + (size_t)blockIdx.z * aS;
    const float* W = W0 + (size_t)blockIdx.z * wS;
    const float* bias = bias0 + (size_t)blockIdx.z * bS;
    float* C = C0 + (size_t)blockIdx.z * cS;

    __shared__ __align__(16) float As[16][68];
    __shared__ __align__(16) float Bs[16][68];
    const int bm = blockIdx.y * 64, bn = blockIdx.x * 64;
    const int tid = threadIdx.x;
    const int tx = tid & 15, ty = tid >> 4;
    const int lrow = tid >> 2, kb = (tid & 3) * 4;

    float acc[4][4] = {};
    const bool aval = (bm + lrow) < M;
    const float* Aptr = A + (size_t)(aval ? (bm + lrow) : 0) * K + kb;
    const float* Wptr = W + (size_t)(bn + lrow) * K + kb;

    for (int k0 = 0; k0 < K; k0 += 16) {
        float4 av = make_float4(0.f, 0.f, 0.f, 0.f);
        if (aval) av = *(const float4*)(Aptr + k0);
        float4 wv = *(const float4*)(Wptr + k0);
        As[kb+0][lrow] = av.x; As[kb+1][lrow] = av.y;
        As[kb+2][lrow] = av.z; As[kb+3][lrow] = av.w;
        Bs[kb+0][lrow] = wv.x; Bs[kb+1][lrow] = wv.y;
        Bs[kb+2][lrow] = wv.z; Bs[kb+3][lrow] = wv.w;
        __syncthreads();
#pragma unroll
        for (int k = 0; k < 16; k++) {
            float ar[4], br[4];
            *(float4*)ar = *(const float4*)&As[k][ty * 4];
            *(float4*)br = *(const float4*)&Bs[k][tx * 4];
#pragma unroll
            for (int i = 0; i < 4; i++)
#pragma unroll
                for (int j = 0; j < 4; j++)
                    acc[i][j] += ar[i] * br[j];
        }
        __syncthreads();
    }
#pragma unroll
    for (int i = 0; i < 4; i++) {
        int mm = bm + ty * 4 + i;
        if (mm < M) {
#pragma unroll
            for (int j = 0; j < 4; j++) {
                int n = bn + tx * 4 + j;
                C[(size_t)mm * N + n] = acc[i][j] + bias[n];
            }
        }
    }
}

// ---------------- embedding + positional encoding (validated verbatim) ------
__global__ void embed_kernel(const int* __restrict__ cap, const float* __restrict__ emb,
                             const float* __restrict__ pos, float* __restrict__ x) {
    int t = blockIdx.x;
    int b = t / SS, s = t % SS;
    int c = cap[b * TT + s];
    const float4* e = (const float4*)(emb + (size_t)c * E);
    const float4* p = (const float4*)(pos + (size_t)s * E);
    float4 a = e[threadIdx.x], q = p[threadIdx.x];
    a.x += q.x; a.y += q.y; a.z += q.z; a.w += q.w;
    ((float4*)(x + (size_t)t * E))[threadIdx.x] = a;
}

// ---------------- causal self-attention (R15-validated verbatim) ------------
#define ATTN_SMEM ((SS*68 + SS*66) * 4)
__global__ void attn_kernel(const float* __restrict__ qkv, __half* __restrict__ ctxh) {
    extern __shared__ float dynsm[];
    float (*Ks)[68] = (float(*)[68])dynsm;
    float (*Vs)[66] = (float(*)[66])(dynsm + SS * 68);
    __shared__ float Ps[8][SS + 1];

    const int bh = blockIdx.x;
    const int b = bh >> 4, h = bh & 15;
    const size_t tokbase = (size_t)b * SS;
    const int tid = threadIdx.x;

    for (int idx = tid; idx < SS * HD; idx += 256) {
        int s = idx >> 6, d = idx & 63;
        const float* base = qkv + (tokbase + s) * (3 * E) + h * HD + d;
        Ks[s][d] = base[E];
        Vs[s][d] = base[2 * E];
    }
    __syncthreads();

    const int warp = tid >> 5, lane = tid & 31;

    for (int q = warp; q < SS; q += 8) {
        const float4* qp = (const float4*)(qkv + (tokbase + q) * (3 * E) + h * HD);
        float4 q4[16];
#pragma unroll
        for (int d = 0; d < 16; d++) q4[d] = qp[d];

        float sc[4];
#pragma unroll
        for (int r = 0; r < 4; r++) {
            int k = lane + 32 * r;
            float sv = -1e30f;
            if (k < SS && k <= q) {
                sv = 0.f;
                const float4* kp = (const float4*)&Ks[k][0];
#pragma unroll
                for (int d = 0; d < 16; d++) {
                    float4 kk = kp[d];
                    sv += q4[d].x * kk.x;
                    sv += q4[d].y * kk.y;
                    sv += q4[d].z * kk.z;
                    sv += q4[d].w * kk.w;
                }
                sv *= 0.125f;
            }
            sc[r] = sv;
        }
        float m = fmaxf(fmaxf(sc[0], sc[1]), fmaxf(sc[2], sc[3]));
#pragma unroll
        for (int o = 16; o; o >>= 1) m = fmaxf(m, __shfl_xor_sync(0xffffffffu, m, o));
        float e4[4], sum = 0.f;
#pragma unroll
        for (int r = 0; r < 4; r++) { e4[r] = __expf(sc[r] - m); sum += e4[r]; }
#pragma unroll
        for (int o = 16; o; o >>= 1) sum += __shfl_xor_sync(0xffffffffu, sum, o);
        float inv = 1.f / sum;
#pragma unroll
        for (int r = 0; r < 4; r++) {
            int k = lane + 32 * r;
            if (k < SS) Ps[warp][k] = e4[r] * inv;
        }
        __syncwarp();

        float c0 = 0.f, c1 = 0.f;
        const int d0 = 2 * lane;
        for (int k = 0; k <= q; k++) {
            float p = Ps[warp][k];
            float2 vv = *(const float2*)&Vs[k][d0];
            c0 += p * vv.x; c1 += p * vv.y;
        }
        __half* op = ctxh + (tokbase + q) * E + h * HD + d0;
        *(__half2*)op = __floats2half2_rn(c0, c1);
        __syncwarp();
    }
}

// -------- fused residual add + LayerNorm (+ optional second residual) -------
__global__ void add_ln_kernel(float* __restrict__ x, const float* __restrict__ r,
                              const float* __restrict__ r2,
                              const float* __restrict__ g, const float* __restrict__ bb,
                              int bcast) {
    const int t = blockIdx.x;
    const int rr = bcast ? (t / SS) : t;
    float* xp = x + (size_t)t * E;
    const float* rp = r + (size_t)rr * E;
    const float* r2p = r2 ? (r2 + (size_t)t * E) : nullptr;
    const int tid = threadIdx.x;

    float v[4], s = 0.f, sq = 0.f;
#pragma unroll
    for (int i = 0; i < 4; i++) {
        int idx = tid + i * 256;
        float a = xp[idx] + rp[idx];
        if (r2p) a += r2p[idx];
        v[i] = a; s += a; sq += a * a;
    }
#pragma unroll
    for (int o = 16; o; o >>= 1) {
        s  += __shfl_xor_sync(0xffffffffu, s,  o);
        sq += __shfl_xor_sync(0xffffffffu, sq, o);
    }
    __shared__ float ss[8], sqs[8];
    if ((tid & 31) == 0) { ss[tid >> 5] = s; sqs[tid >> 5] = sq; }
    __syncthreads();
    float St = 0.f, Qt = 0.f;
#pragma unroll
    for (int i = 0; i < 8; i++) { St += ss[i]; Qt += sqs[i]; }
    float mean = St * (1.f / 1024.f);
    float var  = Qt * (1.f / 1024.f) - mean * mean;
    float rs = rsqrtf(var + 1e-5f);
#pragma unroll
    for (int i = 0; i < 4; i++) {
        int idx = tid + i * 256;
        xp[idx] = (v[i] - mean) * rs * g[idx] + bb[idx];
    }
}

// -------- fused double LayerNorm: x = LN2( LN1(x+y+y2)*g1+b1 + cao_bcast ) ---
__global__ void add_ln2_kernel(float* __restrict__ x, const float* __restrict__ y,
                               const float* __restrict__ y2,
                               const float* __restrict__ cao,
                               const float* __restrict__ g1, const float* __restrict__ b1,
                               const float* __restrict__ g2, const float* __restrict__ b2) {
    const int t = blockIdx.x;
    float* xp = x + (size_t)t * E;
    const float* yp = y + (size_t)t * E;
    const float* y2p = y2 + (size_t)t * E;
    const float* cp = cao + (size_t)(t / SS) * E;
    const int tid = threadIdx.x;
    __shared__ float ss[8], sqs[8];

    float v[4], s = 0.f, sq = 0.f;
#pragma unroll
    for (int i = 0; i < 4; i++) {
        int idx = tid + i * 256;
        float a = xp[idx] + yp[idx] + y2p[idx];
        v[i] = a; s += a; sq += a * a;
    }
#pragma unroll
    for (int o = 16; o; o >>= 1) {
        s  += __shfl_xor_sync(0xffffffffu, s,  o);
        sq += __shfl_xor_sync(0xffffffffu, sq, o);
    }
    if ((tid & 31) == 0) { ss[tid >> 5] = s; sqs[tid >> 5] = sq; }
    __syncthreads();
    float St = 0.f, Qt = 0.f;
#pragma unroll
    for (int i = 0; i < 8; i++) { St += ss[i]; Qt += sqs[i]; }
    float mean = St * (1.f / 1024.f);
    float var  = Qt * (1.f / 1024.f) - mean * mean;
    float rs = rsqrtf(var + 1e-5f);

    float w[4]; s = 0.f; sq = 0.f;
#pragma unroll
    for (int i = 0; i < 4; i++) {
        int idx = tid + i * 256;
        float o1 = (v[i] - mean) * rs * g1[idx] + b1[idx];
        float a = o1 + cp[idx];
        w[i] = a; s += a; sq += a * a;
    }
#pragma unroll
    for (int o = 16; o; o >>= 1) {
        s  += __shfl_xor_sync(0xffffffffu, s,  o);
        sq += __shfl_xor_sync(0xffffffffu, sq, o);
    }
    __syncthreads();
    if ((tid & 31) == 0) { ss[tid >> 5] = s; sqs[tid >> 5] = sq; }
    __syncthreads();
    St = 0.f; Qt = 0.f;
#pragma unroll
    for (int i = 0; i < 8; i++) { St += ss[i]; Qt += sqs[i]; }
    mean = St * (1.f / 1024.f);
    var  = Qt * (1.f / 1024.f) - mean * mean;
    rs = rsqrtf(var + 1e-5f);
#pragma unroll
    for (int i = 0; i < 4; i++) {
        int idx = tid + i * 256;
        xp[idx] = (w[i] - mean) * rs * g2[idx] + b2[idx];
    }
}

// ---------------- zero out[:,0,:] ----------------
__global__ void zero_t0(float* __restrict__ out) {
    int idx = blockIdx.x * 256 + threadIdx.x;
    const int per_b = VO / 4;
    if (idx < BB * per_b) {
        int b = idx / per_b, n = idx % per_b;
        ((float4*)out)[(size_t)b * ((size_t)TT * VO / 4) + n] =
            make_float4(0.f, 0.f, 0.f, 0.f);
    }
}

// ---------------- host-side helpers ----------------
static inline void cvtP(const float* in, __half* out, int R, int K) {
    int n4 = R * (K / 4);
    int blocks = (n4 + 255) / 256;
    if (blocks > 1184) blocks = 1184;
    cvt_plain<<<blocks, 256>>>(in, out, n4);
}
template<int MODE>
static inline void launch_tcw(const __half* A, const float* Wf, const float* bias,
                              float* C, float* C2, __half* Ch,
                              int M, int N, int K3, int sK, int nz) {
    dim3 grid((M + 127) / 128, N / 128, nz);
    gemm_tcw<MODE><<<grid, 256, GTC_SMEM3>>>(A, Wf, bias, C, C2, Ch, M, N, K3, sK);
}

extern "C" void kernel_launch(void* const* d_in, const int* in_sizes, int n_in,
                              void* d_out, int out_size) {
    const float* features = (const float*)d_in[0];
    const int*   captions = (const int*)  d_in[1];
    const float* embed    = (const float*)d_in[2];
    const float* pos      = (const float*)d_in[3];
    const float* sa_w  = (const float*)d_in[4];
    const float* sa_b  = (const float*)d_in[5];
    const float* sa_ow = (const float*)d_in[6];
    const float* sa_ob = (const float*)d_in[7];
    const float* ca_w  = (const float*)d_in[8];
    const float* ca_b  = (const float*)d_in[9];
    const float* ca_ow = (const float*)d_in[10];
    const float* ca_ob = (const float*)d_in[11];
    const float* ln_g  = (const float*)d_in[12];
    const float* ln_b  = (const float*)d_in[13];
    const float* ff_w1 = (const float*)d_in[14];
    const float* ff_b1 = (const float*)d_in[15];
    const float* ff_w2 = (const float*)d_in[16];
    const float* ff_b2 = (const float*)d_in[17];
    const float* out_w = (const float*)d_in[18];
    const float* out_b = (const float*)d_in[19];
    float* out = (float*)d_out;

    float *x, *qkv, *y, *y2, *cav, *cao;
    __half *abf, *cbf, *hbf;
    cudaGetSymbolAddress((void**)&x,   g_x);
    cudaGetSymbolAddress((void**)&qkv, g_qkv);
    cudaGetSymbolAddress((void**)&y,   g_y);
    cudaGetSymbolAddress((void**)&y2,  g_y2);
    cudaGetSymbolAddress((void**)&cav, g_cav);
    cudaGetSymbolAddress((void**)&cao, g_cao);
    cudaGetSymbolAddress((void**)&abf, g_abf);
    cudaGetSymbolAddress((void**)&cbf, g_cbf);
    cudaGetSymbolAddress((void**)&hbf, g_hbf);

    cudaFuncSetAttribute(gemm_tcw<0>, cudaFuncAttributeMaxDynamicSharedMemorySize, GTC_SMEM3);
    cudaFuncSetAttribute(gemm_tcw<1>, cudaFuncAttributeMaxDynamicSharedMemorySize, GTC_SMEM3);
    cudaFuncSetAttribute(gemm_tcw<2>, cudaFuncAttributeMaxDynamicSharedMemorySize, GTC_SMEM3);
    cudaFuncSetAttribute(attn_kernel, cudaFuncAttributeMaxDynamicSharedMemorySize, ATTN_SMEM);

    embed_kernel<<<NTOK, 256>>>(captions, embed, pos, x);

    // cross-attention (depends only on features): all layers up-front, batched.
    gemm_nt_b<<<dim3(E / 64, 1, NL), 256>>>(
        features, ca_w + (size_t)2 * E * E, ca_b + 2 * E, cav, BB, E, E,
        0L, 3L * E * E, 3L * E, (long)BB * E);
    gemm_nt_b<<<dim3(E / 64, 1, NL), 256>>>(
        cav, ca_ow, ca_ob, cao, BB, E, E,
        (long)BB * E, (long)E * E, (long)E, (long)BB * E);

    for (int l = 0; l < NL; l++) {
        // self-attention qkv (1-phase, non-split: 600 CTAs x 16 iters)
        cvtP(x, abf, NTOK, E);
        launch_tcw<0>(abf, sa_w + (size_t)l * 3 * E * E,
                      sa_b + (size_t)l * 3 * E, qkv, nullptr, nullptr,
                      NTOK, 3 * E, E, E, 1);
        attn_kernel<<<BB * NH, 256, ATTN_SMEM>>>(qkv, cbf);

        // output projection (1-phase, split-K=2: 400 CTAs x 8 iters)
        launch_tcw<0>(cbf, sa_ow + (size_t)l * E * E,
                      sa_ob + (size_t)l * E, y, y2, nullptr,
                      NTOK, E, E / 2, E, 2);

        // fused ln1 (x+y+y2) then ln2 (+cao broadcast)
        add_ln2_kernel<<<NTOK, 256>>>(x, y, y2, cao + (size_t)l * BB * E,
                                      ln_g + (size_t)(l * 3 + 0) * E,
                                      ln_b + (size_t)(l * 3 + 0) * E,
                                      ln_g + (size_t)(l * 3 + 1) * E,
                                      ln_b + (size_t)(l * 3 + 1) * E);

        // feed-forward: ff1 writes plain fp16 ReLU directly to hbf
        cvtP(x, abf, NTOK, E);
        launch_tcw<1>(abf, ff_w1 + (size_t)l * FFD * E,
                      ff_b1 + (size_t)l * FFD, nullptr, nullptr, hbf,
                      NTOK, FFD, E, E, 1);
        launch_tcw<0>(hbf, ff_w2 + (size_t)l * E * FFD,
                      ff_b2 + (size_t)l * E, y, y2, nullptr,
                      NTOK, E, FFD / 2, FFD, 2);
        add_ln_kernel<<<NTOK, 256>>>(x, y, y2, ln_g + (size_t)(l * 3 + 2) * E,
                                     ln_b + (size_t)(l * 3 + 2) * E, 0);
    }

    // logits: 1-phase, W fp32 read directly, K3 = E.
    zero_t0<<<(BB * (VO / 4) + 255) / 256, 256>>>(out);
    cvtP(x, abf, NTOK, E);
    launch_tcw<2>(abf, out_w, out_b, out, nullptr, nullptr, NTOK, VO, E, E, 1);
}

// round 17
// speedup vs baseline: 1.2984x; 1.2984x over previous
#include <cuda_runtime.h>
#include <cuda_fp16.h>
#include <math.h>
#include <stdint.h>

#define E   1024
#define NH  16
#define HD  64
#define FFD 4096
#define NL  6
#define VO  32000
#define BB  32
#define TT  100
#define SS  99
#define NTOK (BB*SS)   // 3168

// ---------------- scratch (static device globals; no runtime alloc) ----------------
__device__ float g_x[NTOK*E];
__device__ float g_qkv[NTOK*3*E];
__device__ float g_y[NTOK*E];
__device__ float g_y2[NTOK*E];                 // split-K slice-1 partials
__device__ float g_cav[NL*BB*E];
__device__ float g_cao[NL*BB*E];
__device__ float g_zbias[4096];                // zero-initialized (device globals)
__device__ __half g_abf[(size_t)NTOK*E];       // x fp16 mirror (plain)
__device__ __half g_cbf[(size_t)NTOK*E];       // attn ctx fp16 buffer (plain)
__device__ __half g_hbf[(size_t)NTOK*FFD];     // ff1 output fp16 buffer (plain)
__device__ __half g_wbf[(size_t)VO*E];         // weight fp16 buffer (plain)

// ============================================================================
// PTX helpers (mma.sync / ldmatrix / cp.async — all plain sm_80+ PTX)
// ============================================================================
__device__ __forceinline__ uint32_t smem_u32(const void* p) {
    return (uint32_t)__cvta_generic_to_shared(p);
}
__device__ __forceinline__ void cpa16(uint32_t dst, const void* src, uint32_t sz) {
    asm volatile("cp.async.cg.shared.global [%0], [%1], 16, %2;"
                 :: "r"(dst), "l"(src), "r"(sz) : "memory");
}
__device__ __forceinline__ void cpa_commit() {
    asm volatile("cp.async.commit_group;" ::: "memory");
}
__device__ __forceinline__ void cpa_wait2() {
    asm volatile("cp.async.wait_group 2;" ::: "memory");
}

#define LDSM4(r0, r1, r2, r3, addr) \
    asm volatile("ldmatrix.sync.aligned.m8n8.x4.shared.b16 {%0,%1,%2,%3}, [%4];" \
                 : "=r"(r0), "=r"(r1), "=r"(r2), "=r"(r3) : "r"(addr))

#define MMA16816(c, a, b0, b1) \
    asm volatile("mma.sync.aligned.m16n8k16.row.col.f32.f16.f16.f32 " \
                 "{%0,%1,%2,%3}, {%4,%5,%6,%7}, {%8,%9}, {%0,%1,%2,%3};" \
                 : "+f"((c)[0]), "+f"((c)[1]), "+f"((c)[2]), "+f"((c)[3]) \
                 : "r"((a)[0]), "r"((a)[1]), "r"((a)[2]), "r"((a)[3]), \
                   "r"(b0), "r"(b1))

// ============================================================================
// Tensor-core GEMM (HMMA): mainloop byte-identical to R9..R15-validated kernel.
// Plain fp16 operands, fp32 accumulate.
// K3 = k-extent this CTA iterates; sK = operand row stride.
//   non-split: gridDim.z=1, K3 == K.   split-K=2: gridDim.z=2, K3 = K/2.
// MODE 0: fp32 + bias (split-K aware: slice0->C, slice1->C2 with zero bias)
// MODE 1: ReLU + bias, write plain fp16 to Ch (row stride N)
// MODE 2: fp32 + bias, logits row-remap into out[:,1:,:]
// ============================================================================
#define GSTAGE 32768           // 16KB A + 16KB B per stage
#define GTC_SMEM (4*GSTAGE)    // 128KB

template<int MODE>
__global__ void __launch_bounds__(256, 1)
gemm_tc(const __half* __restrict__ A, const __half* __restrict__ W,
        const float* __restrict__ bias, float* __restrict__ C,
        float* __restrict__ C2, __half* __restrict__ Ch,
        int M, int N, int K3, int sK) {
    extern __shared__ __align__(1024) char dsm[];
    const uint32_t smem = smem_u32(dsm);
    const int tid = threadIdx.x;
    const int warp = tid >> 5, lane = tid & 31;
    const int wm = warp >> 2, wn = warp & 3;
    const int bm = blockIdx.x * 128, bn = blockIdx.y * 128;

    // split-K slice selection (zs == 0 always when gridDim.z == 1)
    const int zs = blockIdx.z;
    const __half* Ab = A + (size_t)zs * K3;
    const __half* Wb = W + (size_t)zs * K3;
    float* Cout = (zs == 0) ? C : C2;
    const float* bv = (zs == 0) ? bias : g_zbias;

    // ---- global->smem load slots: 4 A chunks + 4 B chunks of 16B per thread
    const __half* ag[4]; uint32_t adst[4], asz[4];
    const __half* bg[4]; uint32_t bdst[4];
#pragma unroll
    for (int j = 0; j < 4; j++) {
        int id = tid + j * 256;
        int r = id >> 3, c = id & 7;
        int gr = bm + r;
        bool v = gr < M;
        if (!v) gr = M - 1;
        ag[j] = Ab + (size_t)gr * sK + c * 8;
        asz[j] = v ? 16u : 0u;
        adst[j] = (uint32_t)(r * 128 + ((c ^ (r & 7)) << 4));
        bg[j] = Wb + (size_t)(bn + r) * sK + c * 8;
        bdst[j] = (uint32_t)(16384 + r * 128 + ((c ^ (r & 7)) << 4));
    }

    const int nIter = K3 >> 6;

    // prologue: stages 0,1,2
#pragma unroll
    for (int s = 0; s < 3; s++) {
        uint32_t sb = smem + s * GSTAGE;
        int k0 = s * 64;
        if (s < 1 || s < nIter) {
#pragma unroll
            for (int j = 0; j < 4; j++) cpa16(sb + adst[j], ag[j] + k0, s < nIter ? asz[j] : 0u);
#pragma unroll
            for (int j = 0; j < 4; j++) cpa16(sb + bdst[j], bg[j] + k0, s < nIter ? 16u : 0u);
        }
        cpa_commit();
    }

    // ---- ldmatrix address components
    uint32_t aoff[4], aswz[4];
#pragma unroll
    for (int mi = 0; mi < 4; mi++) {
        int rowa = wm * 64 + mi * 16 + (lane & 15);
        aoff[mi] = rowa * 128;
        aswz[mi] = rowa & 7;
    }
    const uint32_t ahi = lane >> 4;
    uint32_t boff[2], bswz[2];
#pragma unroll
    for (int p = 0; p < 2; p++) {
        int rowb = wn * 32 + p * 16 + (lane & 7) + ((lane >> 4) << 3);
        boff[p] = 16384 + rowb * 128;
        bswz[p] = rowb & 7;
    }
    const uint32_t bhi = (lane >> 3) & 1;

    float acc[4][4][4];
#pragma unroll
    for (int i = 0; i < 4; i++)
#pragma unroll
        for (int j = 0; j < 4; j++)
#pragma unroll
            for (int k = 0; k < 4; k++) acc[i][j][k] = 0.f;

    for (int it = 0; it < nIter; it++) {
        cpa_wait2();
        __syncthreads();

        int ld = it + 3;
        if (ld < nIter) {
            uint32_t sb = smem + (ld & 3) * GSTAGE;
            int k0 = ld * 64;
#pragma unroll
            for (int j = 0; j < 4; j++) cpa16(sb + adst[j], ag[j] + k0, asz[j]);
#pragma unroll
            for (int j = 0; j < 4; j++) cpa16(sb + bdst[j], bg[j] + k0, 16);
        }
        cpa_commit();

        const uint32_t sb = smem + (it & 3) * GSTAGE;
#pragma unroll
        for (int ki = 0; ki < 4; ki++) {
            uint32_t a[4][4], b[2][4];
#pragma unroll
            for (int mi = 0; mi < 4; mi++) {
                uint32_t addr = sb + aoff[mi] + ((((ki << 1) + ahi) ^ aswz[mi]) << 4);
                LDSM4(a[mi][0], a[mi][1], a[mi][2], a[mi][3], addr);
            }
#pragma unroll
            for (int p = 0; p < 2; p++) {
                uint32_t addr = sb + boff[p] + ((((ki << 1) + bhi) ^ bswz[p]) << 4);
                LDSM4(b[p][0], b[p][1], b[p][2], b[p][3], addr);
            }
#pragma unroll
            for (int mi = 0; mi < 4; mi++) {
#pragma unroll
                for (int p = 0; p < 2; p++) {
                    MMA16816(acc[mi][2 * p],     a[mi], b[p][0], b[p][1]);
                    MMA16816(acc[mi][2 * p + 1], a[mi], b[p][2], b[p][3]);
                }
            }
        }
    }

    // ---- epilogue
    const int r0 = bm + wm * 64 + (lane >> 2);
    const int cq = (lane & 3) * 2;
#pragma unroll
    for (int mi = 0; mi < 4; mi++) {
#pragma unroll
        for (int half = 0; half < 2; half++) {
            int row = r0 + mi * 16 + half * 8;
            if (row >= M) continue;
            size_t rowoff;
            if (MODE == 2) {
                int bI = row / SS, sI = row - bI * SS;
                rowoff = (size_t)(bI * TT + sI + 1) * (size_t)N;
            } else {
                rowoff = (size_t)row * (size_t)N;
            }
#pragma unroll
            for (int nt = 0; nt < 4; nt++) {
                int col = bn + wn * 32 + (nt >> 1) * 16 + (nt & 1) * 8 + cq;
                float2 bvv = *(const float2*)(bv + col);
                float vx = acc[mi][nt][2 * half + 0] + bvv.x;
                float vy = acc[mi][nt][2 * half + 1] + bvv.y;
                if (MODE == 1) {
                    vx = fmaxf(vx, 0.f); vy = fmaxf(vy, 0.f);
                    *(__half2*)(Ch + rowoff + col) = __floats2half2_rn(vx, vy);
                } else {
                    *(float2*)(Cout + rowoff + col) = make_float2(vx, vy);
                }
            }
        }
    }
}

// ============================================================================
// fp32 -> fp16 conversion (plain), grid-stride. (weights only now)
// ============================================================================
__global__ void cvt_plain(const float* __restrict__ in, __half* __restrict__ out,
                          int n4) {
    int stride = gridDim.x * 256;
    for (int i = blockIdx.x * 256 + threadIdx.x; i < n4; i += stride) {
        float4 v = ((const float4*)in)[i];
        __half2* o = (__half2*)(out + (size_t)i * 4);
        o[0] = __floats2half2_rn(v.x, v.y);
        o[1] = __floats2half2_rn(v.z, v.w);
    }
}

// ============================================================================
// small SIMT GEMM (batched): cross-attention GEMVs (M=32) — validated verbatim
// ============================================================================
__global__ void gemm_nt_b(const float* __restrict__ A0, const float* __restrict__ W0,
                          const float* __restrict__ bias0, float* __restrict__ C0,
                          int M, int N, int K,
                          long aS, long wS, long bS, long cS) {
    const float* A = A0 + (size_t)blockIdx.z * aS;
    const float* W = W0 + (size_t)blockIdx.z * wS;
    const float* bias = bias0 + (size_t)blockIdx.z * bS;
    float* C = C0 + (size_t)blockIdx.z * cS;

    __shared__ __align__(16) float As[16][68];
    __shared__ __align__(16) float Bs[16][68];
    const int bm = blockIdx.y * 64, bn = blockIdx.x * 64;
    const int tid = threadIdx.x;
    const int tx = tid & 15, ty = tid >> 4;
    const int lrow = tid >> 2, kb = (tid & 3) * 4;

    float acc[4][4] = {};
    const bool aval = (bm + lrow) < M;
    const float* Aptr = A + (size_t)(aval ? (bm + lrow) : 0) * K + kb;
    const float* Wptr = W + (size_t)(bn + lrow) * K + kb;

    for (int k0 = 0; k0 < K; k0 += 16) {
        float4 av = make_float4(0.f, 0.f, 0.f, 0.f);
        if (aval) av = *(const float4*)(Aptr + k0);
        float4 wv = *(const float4*)(Wptr + k0);
        As[kb+0][lrow] = av.x; As[kb+1][lrow] = av.y;
        As[kb+2][lrow] = av.z; As[kb+3][lrow] = av.w;
        Bs[kb+0][lrow] = wv.x; Bs[kb+1][lrow] = wv.y;
        Bs[kb+2][lrow] = wv.z; Bs[kb+3][lrow] = wv.w;
        __syncthreads();
#pragma unroll
        for (int k = 0; k < 16; k++) {
            float ar[4], br[4];
            *(float4*)ar = *(const float4*)&As[k][ty * 4];
            *(float4*)br = *(const float4*)&Bs[k][tx * 4];
#pragma unroll
            for (int i = 0; i < 4; i++)
#pragma unroll
                for (int j = 0; j < 4; j++)
                    acc[i][j] += ar[i] * br[j];
        }
        __syncthreads();
    }
#pragma unroll
    for (int i = 0; i < 4; i++) {
        int mm = bm + ty * 4 + i;
        if (mm < M) {
#pragma unroll
            for (int j = 0; j < 4; j++) {
                int n = bn + tx * 4 + j;
                C[(size_t)mm * N + n] = acc[i][j] + bias[n];
            }
        }
    }
}

// ------- embedding + positional encoding, also emits fp16 x mirror ----------
__global__ void embed_kernel(const int* __restrict__ cap, const float* __restrict__ emb,
                             const float* __restrict__ pos, float* __restrict__ x,
                             __half* __restrict__ xh) {
    int t = blockIdx.x;
    int b = t / SS, s = t % SS;
    int c = cap[b * TT + s];
    const float4* e = (const float4*)(emb + (size_t)c * E);
    const float4* p = (const float4*)(pos + (size_t)s * E);
    float4 a = e[threadIdx.x], q = p[threadIdx.x];
    a.x += q.x; a.y += q.y; a.z += q.z; a.w += q.w;
    ((float4*)(x + (size_t)t * E))[threadIdx.x] = a;
    __half2* oh = (__half2*)(xh + (size_t)t * E + threadIdx.x * 4);
    oh[0] = __floats2half2_rn(a.x, a.y);
    oh[1] = __floats2half2_rn(a.z, a.w);
}

// ---------------- causal self-attention (R15-validated verbatim) ------------
#define ATTN_SMEM ((SS*68 + SS*66) * 4)
__global__ void attn_kernel(const float* __restrict__ qkv, __half* __restrict__ ctxh) {
    extern __shared__ float dynsm[];
    float (*Ks)[68] = (float(*)[68])dynsm;
    float (*Vs)[66] = (float(*)[66])(dynsm + SS * 68);
    __shared__ float Ps[8][SS + 1];

    const int bh = blockIdx.x;
    const int b = bh >> 4, h = bh & 15;
    const size_t tokbase = (size_t)b * SS;
    const int tid = threadIdx.x;

    for (int idx = tid; idx < SS * HD; idx += 256) {
        int s = idx >> 6, d = idx & 63;
        const float* base = qkv + (tokbase + s) * (3 * E) + h * HD + d;
        Ks[s][d] = base[E];
        Vs[s][d] = base[2 * E];
    }
    __syncthreads();

    const int warp = tid >> 5, lane = tid & 31;

    for (int q = warp; q < SS; q += 8) {
        const float4* qp = (const float4*)(qkv + (tokbase + q) * (3 * E) + h * HD);
        float4 q4[16];
#pragma unroll
        for (int d = 0; d < 16; d++) q4[d] = qp[d];

        float sc[4];
#pragma unroll
        for (int r = 0; r < 4; r++) {
            int k = lane + 32 * r;
            float sv = -1e30f;
            if (k < SS && k <= q) {
                sv = 0.f;
                const float4* kp = (const float4*)&Ks[k][0];
#pragma unroll
                for (int d = 0; d < 16; d++) {
                    float4 kk = kp[d];
                    sv += q4[d].x * kk.x;
                    sv += q4[d].y * kk.y;
                    sv += q4[d].z * kk.z;
                    sv += q4[d].w * kk.w;
                }
                sv *= 0.125f;
            }
            sc[r] = sv;
        }
        float m = fmaxf(fmaxf(sc[0], sc[1]), fmaxf(sc[2], sc[3]));
#pragma unroll
        for (int o = 16; o; o >>= 1) m = fmaxf(m, __shfl_xor_sync(0xffffffffu, m, o));
        float e4[4], sum = 0.f;
#pragma unroll
        for (int r = 0; r < 4; r++) { e4[r] = __expf(sc[r] - m); sum += e4[r]; }
#pragma unroll
        for (int o = 16; o; o >>= 1) sum += __shfl_xor_sync(0xffffffffu, sum, o);
        float inv = 1.f / sum;
#pragma unroll
        for (int r = 0; r < 4; r++) {
            int k = lane + 32 * r;
            if (k < SS) Ps[warp][k] = e4[r] * inv;
        }
        __syncwarp();

        float c0 = 0.f, c1 = 0.f;
        const int d0 = 2 * lane;
        for (int k = 0; k <= q; k++) {
            float p = Ps[warp][k];
            float2 vv = *(const float2*)&Vs[k][d0];
            c0 += p * vv.x; c1 += p * vv.y;
        }
        __half* op = ctxh + (tokbase + q) * E + h * HD + d0;
        *(__half2*)op = __floats2half2_rn(c0, c1);
        __syncwarp();
    }
}

// -- fused residual add + LayerNorm (+ second residual), emits fp16 x mirror -
__global__ void add_ln_kernel(float* __restrict__ x, const float* __restrict__ r,
                              const float* __restrict__ r2,
                              const float* __restrict__ g, const float* __restrict__ bb,
                              __half* __restrict__ xh) {
    const int t = blockIdx.x;
    float* xp = x + (size_t)t * E;
    const float* rp = r + (size_t)t * E;          // bcast NOT used here (ff path)
    const float* r2p = r2 + (size_t)t * E;
    const int tid = threadIdx.x;

    float v[4], s = 0.f, sq = 0.f;
#pragma unroll
    for (int i = 0; i < 4; i++) {
        int idx = tid + i * 256;
        float a = xp[idx] + rp[idx] + r2p[idx];
        v[i] = a; s += a; sq += a * a;
    }
#pragma unroll
    for (int o = 16; o; o >>= 1) {
        s  += __shfl_xor_sync(0xffffffffu, s,  o);
        sq += __shfl_xor_sync(0xffffffffu, sq, o);
    }
    __shared__ float ss[8], sqs[8];
    if ((tid & 31) == 0) { ss[tid >> 5] = s; sqs[tid >> 5] = sq; }
    __syncthreads();
    float St = 0.f, Qt = 0.f;
#pragma unroll
    for (int i = 0; i < 8; i++) { St += ss[i]; Qt += sqs[i]; }
    float mean = St * (1.f / 1024.f);
    float var  = Qt * (1.f / 1024.f) - mean * mean;
    float rs = rsqrtf(var + 1e-5f);
#pragma unroll
    for (int i = 0; i < 4; i++) {
        int idx = tid + i * 256;
        float o = (v[i] - mean) * rs * g[idx] + bb[idx];
        xp[idx] = o;
        xh[(size_t)t * E + idx] = __float2half_rn(o);
    }
}

// -- fused double LayerNorm: x = LN2( LN1(x+y+y2)*g1+b1 + cao_bcast ), -------
// emits fp16 x mirror (feeds ff1). R10-validated arithmetic.
__global__ void add_ln2_kernel(float* __restrict__ x, const float* __restrict__ y,
                               const float* __restrict__ y2,
                               const float* __restrict__ cao,
                               const float* __restrict__ g1, const float* __restrict__ b1,
                               const float* __restrict__ g2, const float* __restrict__ b2,
                               __half* __restrict__ xh) {
    const int t = blockIdx.x;
    float* xp = x + (size_t)t * E;
    const float* yp = y + (size_t)t * E;
    const float* y2p = y2 + (size_t)t * E;
    const float* cp = cao + (size_t)(t / SS) * E;   // cross-attn residual IS broadcast
    const int tid = threadIdx.x;
    __shared__ float ss[8], sqs[8];

    float v[4], s = 0.f, sq = 0.f;
#pragma unroll
    for (int i = 0; i < 4; i++) {
        int idx = tid + i * 256;
        float a = xp[idx] + yp[idx] + y2p[idx];
        v[i] = a; s += a; sq += a * a;
    }
#pragma unroll
    for (int o = 16; o; o >>= 1) {
        s  += __shfl_xor_sync(0xffffffffu, s,  o);
        sq += __shfl_xor_sync(0xffffffffu, sq, o);
    }
    if ((tid & 31) == 0) { ss[tid >> 5] = s; sqs[tid >> 5] = sq; }
    __syncthreads();
    float St = 0.f, Qt = 0.f;
#pragma unroll
    for (int i = 0; i < 8; i++) { St += ss[i]; Qt += sqs[i]; }
    float mean = St * (1.f / 1024.f);
    float var  = Qt * (1.f / 1024.f) - mean * mean;
    float rs = rsqrtf(var + 1e-5f);

    float w[4]; s = 0.f; sq = 0.f;
#pragma unroll
    for (int i = 0; i < 4; i++) {
        int idx = tid + i * 256;
        float o1 = (v[i] - mean) * rs * g1[idx] + b1[idx];
        float a = o1 + cp[idx];
        w[i] = a; s += a; sq += a * a;
    }
#pragma unroll
    for (int o = 16; o; o >>= 1) {
        s  += __shfl_xor_sync(0xffffffffu, s,  o);
        sq += __shfl_xor_sync(0xffffffffu, sq, o);
    }
    __syncthreads();
    if ((tid & 31) == 0) { ss[tid >> 5] = s; sqs[tid >> 5] = sq; }
    __syncthreads();
    St = 0.f; Qt = 0.f;
#pragma unroll
    for (int i = 0; i < 8; i++) { St += ss[i]; Qt += sqs[i]; }
    mean = St * (1.f / 1024.f);
    var  = Qt * (1.f / 1024.f) - mean * mean;
    rs = rsqrtf(var + 1e-5f);
#pragma unroll
    for (int i = 0; i < 4; i++) {
        int idx = tid + i * 256;
        float o = (w[i] - mean) * rs * g2[idx] + b2[idx];
        xp[idx] = o;
        xh[(size_t)t * E + idx] = __float2half_rn(o);
    }
}

// ---------------- zero out[:,0,:] ----------------
__global__ void zero_t0(float* __restrict__ out) {
    int idx = blockIdx.x * 256 + threadIdx.x;
    const int per_b = VO / 4;
    if (idx < BB * per_b) {
        int b = idx / per_b, n = idx % per_b;
        ((float4*)out)[(size_t)b * ((size_t)TT * VO / 4) + n] =
            make_float4(0.f, 0.f, 0.f, 0.f);
    }
}

// ---------------- host-side helpers ----------------
static inline void cvtP(const float* in, __half* out, int R, int K) {
    int n4 = R * (K / 4);
    int blocks = (n4 + 255) / 256;
    if (blocks > 1184) blocks = 1184;
    cvt_plain<<<blocks, 256>>>(in, out, n4);
}
template<int MODE>
static inline void launch_tc(const __half* A, const __half* W, const float* bias,
                             float* C, float* C2, __half* Ch,
                             int M, int N, int K3, int sK, int nz) {
    dim3 grid((M + 127) / 128, N / 128, nz);
    gemm_tc<MODE><<<grid, 256, GTC_SMEM>>>(A, W, bias, C, C2, Ch, M, N, K3, sK);
}

extern "C" void kernel_launch(void* const* d_in, const int* in_sizes, int n_in,
                              void* d_out, int out_size) {
    const float* features = (const float*)d_in[0];
    const int*   captions = (const int*)  d_in[1];
    const float* embed    = (const float*)d_in[2];
    const float* pos      = (const float*)d_in[3];
    const float* sa_w  = (const float*)d_in[4];
    const float* sa_b  = (const float*)d_in[5];
    const float* sa_ow = (const float*)d_in[6];
    const float* sa_ob = (const float*)d_in[7];
    const float* ca_w  = (const float*)d_in[8];
    const float* ca_b  = (const float*)d_in[9];
    const float* ca_ow = (const float*)d_in[10];
    const float* ca_ob = (const float*)d_in[11];
    const float* ln_g  = (const float*)d_in[12];
    const float* ln_b  = (const float*)d_in[13];
    const float* ff_w1 = (const float*)d_in[14];
    const float* ff_b1 = (const float*)d_in[15];
    const float* ff_w2 = (const float*)d_in[16];
    const float* ff_b2 = (const float*)d_in[17];
    const float* out_w = (const float*)d_in[18];
    const float* out_b = (const float*)d_in[19];
    float* out = (float*)d_out;

    float *x, *qkv, *y, *y2, *cav, *cao;
    __half *abf, *cbf, *hbf, *wbf;
    cudaGetSymbolAddress((void**)&x,   g_x);
    cudaGetSymbolAddress((void**)&qkv, g_qkv);
    cudaGetSymbolAddress((void**)&y,   g_y);
    cudaGetSymbolAddress((void**)&y2,  g_y2);
    cudaGetSymbolAddress((void**)&cav, g_cav);
    cudaGetSymbolAddress((void**)&cao, g_cao);
    cudaGetSymbolAddress((void**)&abf, g_abf);
    cudaGetSymbolAddress((void**)&cbf, g_cbf);
    cudaGetSymbolAddress((void**)&hbf, g_hbf);
    cudaGetSymbolAddress((void**)&wbf, g_wbf);

    cudaFuncSetAttribute(gemm_tc<0>, cudaFuncAttributeMaxDynamicSharedMemorySize, GTC_SMEM);
    cudaFuncSetAttribute(gemm_tc<1>, cudaFuncAttributeMaxDynamicSharedMemorySize, GTC_SMEM);
    cudaFuncSetAttribute(gemm_tc<2>, cudaFuncAttributeMaxDynamicSharedMemorySize, GTC_SMEM);
    cudaFuncSetAttribute(attn_kernel, cudaFuncAttributeMaxDynamicSharedMemorySize, ATTN_SMEM);

    // embed also emits fp16 x mirror (layer-0 qkv input)
    embed_kernel<<<NTOK, 256>>>(captions, embed, pos, x, abf);

    // cross-attention (depends only on features): all layers up-front, batched.
    gemm_nt_b<<<dim3(E / 64, 1, NL), 256>>>(
        features, ca_w + (size_t)2 * E * E, ca_b + 2 * E, cav, BB, E, E,
        0L, 3L * E * E, 3L * E, (long)BB * E);
    gemm_nt_b<<<dim3(E / 64, 1, NL), 256>>>(
        cav, ca_ow, ca_ob, cao, BB, E, E,
        (long)BB * E, (long)E * E, (long)E, (long)BB * E);

    for (int l = 0; l < NL; l++) {
        // self-attention qkv (1-phase, non-split: 600 CTAs x 16 iters)
        cvtP(sa_w + (size_t)l * 3 * E * E, wbf, 3 * E, E);
        launch_tc<0>(abf, wbf, sa_b + (size_t)l * 3 * E, qkv, nullptr, nullptr,
                     NTOK, 3 * E, E, E, 1);
        attn_kernel<<<BB * NH, 256, ATTN_SMEM>>>(qkv, cbf);

        // output projection (1-phase, split-K=2: 400 CTAs x 8 iters)
        cvtP(sa_ow + (size_t)l * E * E, wbf, E, E);
        launch_tc<0>(cbf, wbf, sa_ob + (size_t)l * E, y, y2, nullptr,
                     NTOK, E, E / 2, E, 2);

        // fused ln1 (x+y+y2) then ln2 (+cao broadcast); emits fp16 x -> abf
        add_ln2_kernel<<<NTOK, 256>>>(x, y, y2, cao + (size_t)l * BB * E,
                                      ln_g + (size_t)(l * 3 + 0) * E,
                                      ln_b + (size_t)(l * 3 + 0) * E,
                                      ln_g + (size_t)(l * 3 + 1) * E,
                                      ln_b + (size_t)(l * 3 + 1) * E, abf);

        // feed-forward: ff1 writes plain fp16 ReLU directly to hbf
        cvtP(ff_w1 + (size_t)l * FFD * E, wbf, FFD, E);
        launch_tc<1>(abf, wbf, ff_b1 + (size_t)l * FFD, nullptr, nullptr, hbf,
                     NTOK, FFD, E, E, 1);
        cvtP(ff_w2 + (size_t)l * E * FFD, wbf, E, FFD);
        launch_tc<0>(hbf, wbf, ff_b2 + (size_t)l * E, y, y2, nullptr,
                     NTOK, E, FFD / 2, FFD, 2);
        // ff residual LN (per-token residuals; NO broadcast); emits fp16 x -> abf
        add_ln_kernel<<<NTOK, 256>>>(x, y, y2, ln_g + (size_t)(l * 3 + 2) * E,
                                     ln_b + (size_t)(l * 3 + 2) * E, abf);
    }

    // logits: 1-phase (x_hi * W_hi), K3 = E; abf already holds fp16 x.
    zero_t0<<<(BB * (VO / 4) + 255) / 256, 256>>>(out);
    cvtP(out_w, wbf, VO, E);
    launch_tc<2>(abf, wbf, out_b, out, nullptr, nullptr, NTOK, VO, E, E, 1);
}